// round 15
// baseline (speedup 1.0000x reference)
#include <cuda_runtime.h>
#include <cuda_bf16.h>
#include <math.h>
#include <stdint.h>

// Problem constants
#define NTOK 65536   // B * Lq = 4 * 16384
#define LQ   16384
#define DM   128
#define NHH  4
#define NPP  4
#define HDD  32
#define FFD  512
#define GW   128
#define GH   128

// ---------------- device scratch ----------------
__device__ __align__(16) float g_q[NTOK * DM];                     // running query
__device__ __align__(16) __nv_bfloat16 g_value[2 * NTOK * DM];     // value (bf16, both layers)
// bf16 transposed weights: per layer [vp 128x128][op 128x128][l1 512x128][l2 128x512]
#define WB_LAYER 163840
#define WB_VP 0
#define WB_OP 16384
#define WB_L1 32768
#define WB_L2 98304
__device__ __align__(16) __nv_bfloat16 g_wb[2 * WB_LAYER];
// combined sampling-param weights: per layer [64 rows][128] bf16
__device__ __align__(16) __nv_bfloat16 g_wso[2 * 64 * 128];

// ---------------- helpers ----------------
__device__ __forceinline__ uint32_t smem_u32(const void* p) {
    uint32_t a;
    asm("{ .reg .u64 t; cvta.to.shared.u64 t, %1; cvt.u32.u64 %0, t; }" : "=r"(a) : "l"(p));
    return a;
}
__device__ __forceinline__ uint32_t pack_bf16(float x, float y) {
    __nv_bfloat162 h = __floats2bfloat162_rn(x, y);
    return *(uint32_t*)&h;
}
__device__ __forceinline__ float2 unpk(uint32_t u) {
    return __bfloat1622float2(*(__nv_bfloat162*)&u);
}
__device__ __forceinline__ void ldsm4(uint32_t& r0, uint32_t& r1, uint32_t& r2, uint32_t& r3,
                                      uint32_t addr) {
    asm volatile("ldmatrix.sync.aligned.m8n8.x4.shared.b16 {%0,%1,%2,%3}, [%4];"
                 : "=r"(r0), "=r"(r1), "=r"(r2), "=r"(r3) : "r"(addr));
}
__device__ __forceinline__ void mma16816(float* c, uint32_t a0, uint32_t a1, uint32_t a2,
                                         uint32_t a3, uint32_t b0, uint32_t b1) {
    asm volatile(
        "mma.sync.aligned.m16n8k16.row.col.f32.bf16.bf16.f32 "
        "{%0,%1,%2,%3}, {%4,%5,%6,%7}, {%8,%9}, {%0,%1,%2,%3};"
        : "+f"(c[0]), "+f"(c[1]), "+f"(c[2]), "+f"(c[3])
        : "r"(a0), "r"(a1), "r"(a2), "r"(a3), "r"(b0), "r"(b1));
}

// ---------------------------------------------------------------------------
// Weight prep: W[K][N] fp32 -> Wb[N][K] bf16 for all matrices + so/aw combo.
// ---------------------------------------------------------------------------
#define PREP_TOTAL (2 * WB_LAYER + 2 * 64 * 128)
__global__ void __launch_bounds__(256) prep_weights(
    const float* __restrict__ vp_w, const float* __restrict__ op_w,
    const float* __restrict__ l1_w, const float* __restrict__ l2_w,
    const float* __restrict__ so_w, const float* __restrict__ aw_w)
{
    int idx = blockIdx.x * 256 + threadIdx.x;
    if (idx >= PREP_TOTAL) return;
    if (idx < 2 * WB_LAYER) {
        int l = idx / WB_LAYER;
        int r = idx % WB_LAYER;
        const float* W; int K, N, off;
        if (r < 16384)       { W = vp_w + l * 16384; K = 128; N = 128; off = WB_VP; }
        else if (r < 32768)  { W = op_w + l * 16384; r -= 16384; K = 128; N = 128; off = WB_OP; }
        else if (r < 98304)  { W = l1_w + l * 65536; r -= 32768; K = 128; N = 512; off = WB_L1; }
        else                 { W = l2_w + l * 65536; r -= 98304; K = 512; N = 128; off = WB_L2; }
        int n = r / K, k = r % K;
        g_wb[l * WB_LAYER + off + r] = __float2bfloat16(W[k * N + n]);
    } else {
        int r2 = idx - 2 * WB_LAYER;     // 0..16383
        int l = r2 / 8192; r2 -= l * 8192;
        int n = r2 / 128, k = r2 % 128;
        float v = 0.0f;
        if (n < 32)      v = so_w[(size_t)l * 128 * 32 + k * 32 + n];
        else if (n < 48) v = aw_w[(size_t)l * 128 * 16 + k * 16 + (n - 32)];
        g_wso[(size_t)l * 8192 + n * 128 + k] = __float2bfloat16(v);
    }
}

// ---------------------------------------------------------------------------
// Value projection, BOTH layers, reading src once. bf16 output. 16B staging.
// ---------------------------------------------------------------------------
#define VP_SMEM (4 * 9216 * 2)
__global__ void __launch_bounds__(256, 2) gemm_vp(
    const float* __restrict__ src, const float* __restrict__ vp_b)
{
    extern __shared__ __align__(16) uint8_t smraw[];
    __nv_bfloat16* sA = (__nv_bfloat16*)smraw;   // 2 x 9216
    __nv_bfloat16* sB = sA + 2 * 9216;           // 2 x 9216
    __shared__ float s_bias[128];

    const int tid  = threadIdx.x;
    const int wid  = tid >> 5;
    const int lane = tid & 31;
    const int row0 = blockIdx.x * 128;
    const int lr   = tid >> 4;
    const int lc4  = (tid & 15) * 4;
    const int wr   = tid >> 3;             // 0..31
    const int wc8  = (tid & 7) * 8;        // 0..56

    // stage src tile once (fp32 -> bf16)
#pragma unroll
    for (int p = 0; p < 2; p++)
#pragma unroll
        for (int i = 0; i < 8; i++) {
            int r = lr + i * 16;
            float4 v = *(const float4*)(src + (size_t)(row0 + r) * 128 + p * 64 + lc4);
            uint2 pk; pk.x = pack_bf16(v.x, v.y); pk.y = pack_bf16(v.z, v.w);
            *(uint2*)&sA[p * 9216 + r * 72 + lc4] = pk;
        }

    for (int layer = 0; layer < 2; layer++) {
        const __nv_bfloat16* Wb = g_wb + (size_t)layer * WB_LAYER + WB_VP;
        __nv_bfloat16* outp = g_value + (size_t)layer * NTOK * DM;
        if (layer) __syncthreads();
        if (tid < 128) s_bias[tid] = vp_b[layer * DM + tid];
#pragma unroll
        for (int p = 0; p < 2; p++)
#pragma unroll
            for (int i = 0; i < 4; i++) {
                int r = wr + i * 32;
                uint4 w = *(const uint4*)(Wb + (size_t)r * 128 + p * 64 + wc8);
                *(uint4*)&sB[p * 9216 + r * 72 + wc8] = w;
            }
        __syncthreads();

        float c[16][4];
#pragma unroll
        for (int b = 0; b < 16; b++)
#pragma unroll
            for (int j = 0; j < 4; j++) c[b][j] = 0.0f;
#pragma unroll
        for (int p = 0; p < 2; p++)
#pragma unroll
            for (int ks = 0; ks < 4; ks++) {
                uint32_t a0, a1, a2, a3;
                uint32_t aaddr = smem_u32(&sA[p * 9216 + (wid * 16 + (lane & 15)) * 72 +
                                              ks * 16 + (lane >> 4) * 8]);
                ldsm4(a0, a1, a2, a3, aaddr);
#pragma unroll
                for (int nb = 0; nb < 8; nb++) {
                    uint32_t b0, b1, b2, b3;
                    uint32_t baddr = smem_u32(&sB[p * 9216 + (nb * 16 + (lane & 15)) * 72 +
                                                  ks * 16 + (lane >> 4) * 8]);
                    ldsm4(b0, b1, b2, b3, baddr);
                    mma16816(c[nb * 2 + 0], a0, a1, a2, a3, b0, b2);
                    mma16816(c[nb * 2 + 1], a0, a1, a2, a3, b1, b3);
                }
            }

        const int qr = lane >> 2;
        const int qc = (lane & 3) * 2;
        const int r0 = row0 + wid * 16 + qr;
        const int r1 = r0 + 8;
#pragma unroll
        for (int b = 0; b < 16; b++) {
            int lcn = b * 8 + qc;
            *(uint32_t*)&outp[(size_t)r0 * 128 + lcn] =
                pack_bf16(c[b][0] + s_bias[lcn], c[b][1] + s_bias[lcn + 1]);
            *(uint32_t*)&outp[(size_t)r1 * 128 + lcn] =
                pack_bf16(c[b][2] + s_bias[lcn], c[b][3] + s_bias[lcn + 1]);
        }
    }
}

// ---------------------------------------------------------------------------
// Fully fused deformable attention with overlaid phase buffers (R12, 319.9us).
// ---------------------------------------------------------------------------
#define ATT_SMEM (18432 + 36864 + 17408)
__global__ void __launch_bounds__(256, 3) attn_fused(
    const __nv_bfloat16* __restrict__ value, const __nv_bfloat16* __restrict__ Wop,
    const float* __restrict__ op_bias, const float* __restrict__ so_b,
    const float* __restrict__ aw_b, const float* __restrict__ qsrc,
    const float* __restrict__ pos, const __nv_bfloat16* __restrict__ Wso,
    const float* __restrict__ lng, const float* __restrict__ lnb,
    float* __restrict__ outp)
{
    extern __shared__ __align__(16) uint8_t smraw[];
    __nv_bfloat16* sA  = (__nv_bfloat16*)smraw;      // 2 panels x (64 x 72)
    __nv_bfloat16* sB  = sA + 2 * 4608;              // 2 panels x (128 x 72)
    uint8_t* region = (uint8_t*)(sB + 2 * 9216);     // 17408B overlay
    __nv_bfloat16* sWc = (__nv_bfloat16*)region;     // 2 panels x (48 x 72)
    float*  sOuts = (float*)region;                  // 64 x 68
    float2* sLoc  = (float2*)region;                 // [64][16] (px,py)  (8192B)
    float*  sAw   = (float*)(region + 8192);         // [64][16]          (4096B)
    __shared__ float s_bias[128], s_g[128], s_b[128], s_pb[64];
    __shared__ float2 sLN[64][2];

    const int tid  = threadIdx.x;
    const int wid  = tid >> 5;
    const int lane = tid & 31;
    const int row0 = blockIdx.x * 64;
    const int batch = row0 >> 14;
    const int lr   = tid >> 4;
    const int lc4  = (tid & 15) * 4;
    const int wr   = tid >> 3;             // 0..31
    const int wc8  = (tid & 7) * 8;        // 0..56

    if (tid < 128) { s_bias[tid] = op_bias[tid]; s_g[tid] = lng[tid]; s_b[tid] = lnb[tid]; }
    else if (tid < 192) {
        int o = tid - 128;
        s_pb[o] = (o < 32) ? so_b[o] : ((o < 48) ? aw_b[o - 32] : 0.0f);
    }

    // ---- phase 0: stage qin (bf16), Wso (48 rows), op weights ----
#pragma unroll
    for (int p = 0; p < 2; p++)
#pragma unroll
        for (int i = 0; i < 4; i++) {
            int r = lr + i * 16;
            int col = p * 64 + lc4;
            float4 qv = *(const float4*)(qsrc + (size_t)(row0 + r) * 128 + col);
            float4 pv = *(const float4*)(pos  + (size_t)(row0 + r) * 128 + col);
            uint2 pk;
            pk.x = pack_bf16(qv.x + pv.x, qv.y + pv.y);
            pk.y = pack_bf16(qv.z + pv.z, qv.w + pv.w);
            *(uint2*)&sA[p * 4608 + r * 72 + lc4] = pk;
        }
#pragma unroll
    for (int p = 0; p < 2; p++) {
#pragma unroll
        for (int i = 0; i < 2; i++) {
            int r = wr + i * 32;
            if (r < 48) {
                uint4 w = *(const uint4*)(Wso + (size_t)r * 128 + p * 64 + wc8);
                *(uint4*)&sWc[p * 3456 + r * 72 + wc8] = w;
            }
        }
#pragma unroll
        for (int i = 0; i < 4; i++) {
            int r = wr + i * 32;
            uint4 w = *(const uint4*)(Wop + (size_t)r * 128 + p * 64 + wc8);
            *(uint4*)&sB[p * 9216 + r * 72 + wc8] = w;
        }
    }
    __syncthreads();

    const int mt = wid >> 1;
    const int nh = wid & 1;
    const int qr = lane >> 2;
    const int qc = (lane & 3) * 2;

    // ---- phase 1: params HMMA ----
    {
        float cp[4][4];
#pragma unroll
        for (int b = 0; b < 4; b++)
#pragma unroll
            for (int j = 0; j < 4; j++) cp[b][j] = 0.0f;
        const int nbmax = (nh == 0) ? 2 : 1;
#pragma unroll
        for (int p = 0; p < 2; p++)
#pragma unroll
            for (int ks = 0; ks < 4; ks++) {
                uint32_t a0, a1, a2, a3;
                uint32_t aaddr = smem_u32(&sA[p * 4608 + (mt * 16 + (lane & 15)) * 72 +
                                              ks * 16 + (lane >> 4) * 8]);
                ldsm4(a0, a1, a2, a3, aaddr);
                for (int nb = 0; nb < nbmax; nb++) {
                    uint32_t b0, b1, b2, b3;
                    uint32_t baddr = smem_u32(&sWc[p * 3456 +
                                                   (nh * 32 + nb * 16 + (lane & 15)) * 72 +
                                                   ks * 16 + (lane >> 4) * 8]);
                    ldsm4(b0, b1, b2, b3, baddr);
                    mma16816(cp[nb * 2 + 0], a0, a1, a2, a3, b0, b2);
                    mma16816(cp[nb * 2 + 1], a0, a1, a2, a3, b1, b3);
                }
            }
        __syncthreads();
        const int lrow0 = mt * 16 + qr, lrow1 = lrow0 + 8;
        for (int b = 0; b < 2 * nbmax; b++) {
            int col = nh * 32 + b * 8 + qc;
            sOuts[lrow0 * 68 + col]     = cp[b][0] + s_pb[col];
            sOuts[lrow0 * 68 + col + 1] = cp[b][1] + s_pb[col + 1];
            sOuts[lrow1 * 68 + col]     = cp[b][2] + s_pb[col];
            sOuts[lrow1 * 68 + col + 1] = cp[b][3] + s_pb[col + 1];
        }
    }
    __syncthreads();

    // ---- phase 2: softmax + pixel locations ----
    {
        const int tk = tid >> 2, h = tid & 3;
        const int gq = row0 + tk;
        const float* ob = &sOuts[tk * 68];
        float offs[8];
#pragma unroll
        for (int i = 0; i < 8; i++) offs[i] = ob[h * 8 + i];
        float lg0 = ob[32 + h * 4 + 0];
        float lg1 = ob[32 + h * 4 + 1];
        float lg2 = ob[32 + h * 4 + 2];
        float lg3 = ob[32 + h * 4 + 3];
        __syncthreads();
        float m = fmaxf(fmaxf(lg0, lg1), fmaxf(lg2, lg3));
        float e0 = expf(lg0 - m), e1 = expf(lg1 - m), e2 = expf(lg2 - m), e3 = expf(lg3 - m);
        float inv = 1.0f / (e0 + e1 + e2 + e3);
        float jx = (float)(gq & (GW - 1));
        float iy = (float)((gq >> 7) & (GH - 1));
#pragma unroll
        for (int p = 0; p < 4; p++)
            sLoc[tk * 16 + h * 4 + p] = make_float2(jx + offs[p * 2], iy + offs[p * 2 + 1]);
        sAw[tk * 16 + h * 4 + 0] = e0 * inv;
        sAw[tk * 16 + h * 4 + 1] = e1 * inv;
        sAw[tk * 16 + h * 4 + 2] = e2 * inv;
        sAw[tk * 16 + h * 4 + 3] = e3 * inv;
    }
    __syncthreads();

    // ---- phase 3: bilinear sampling into sA ----
    {
        const int half = lane >> 4;
        const int l16  = lane & 15;
        const int h    = l16 >> 2;
        const int cg   = l16 & 3;
        const __nv_bfloat16* vplane = value + (size_t)batch * LQ * DM + h * HDD + cg * 8;

#pragma unroll
        for (int it = 0; it < 4; it++) {
            const int rloc = wid * 8 + it * 2 + half;
            const int pbase = rloc * 16 + h * 4;

            float a0 = 0.f, a1 = 0.f, a2 = 0.f, a3 = 0.f;
            float a4 = 0.f, a5 = 0.f, a6 = 0.f, a7 = 0.f;
#pragma unroll
            for (int p = 0; p < 4; p++) {
                float2 lp = sLoc[pbase + p];
                float aw = sAw[pbase + p];
                float px = lp.x, py = lp.y;
                float fx = floorf(px), fy = floorf(py);
                int x0 = (int)fx, y0 = (int)fy;
                float wx = px - fx, wy = py - fy;
                float w00 = (1.0f - wx) * (1.0f - wy) * aw;
                float w10 = wx * (1.0f - wy) * aw;
                float w01 = (1.0f - wx) * wy * aw;
                float w11 = wx * wy * aw;
                int x1 = x0 + 1, y1 = y0 + 1;
                bool bx0 = (x0 >= 0) & (x0 < GW);
                bool bx1 = (x1 >= 0) & (x1 < GW);
                bool by0 = (y0 >= 0) & (y0 < GH);
                bool by1 = (y1 >= 0) & (y1 < GH);
#define GATHER(wgt, xx, yy) do { \
                    uint4 v = *(const uint4*)&vplane[((size_t)(yy) * GW + (xx)) * DM]; \
                    float2 f0 = unpk(v.x), f1 = unpk(v.y), f2 = unpk(v.z), f3 = unpk(v.w); \
                    a0 += (wgt) * f0.x; a1 += (wgt) * f0.y; \
                    a2 += (wgt) * f1.x; a3 += (wgt) * f1.y; \
                    a4 += (wgt) * f2.x; a5 += (wgt) * f2.y; \
                    a6 += (wgt) * f3.x; a7 += (wgt) * f3.y; \
                } while (0)
                if (bx0 & by0) GATHER(w00, x0, y0);
                if (bx1 & by0) GATHER(w10, x1, y0);
                if (bx0 & by1) GATHER(w01, x0, y1);
                if (bx1 & by1) GATHER(w11, x1, y1);
#undef GATHER
            }
            const int c   = h * HDD + cg * 8;
            const int pnl = c >> 6, cw = c & 63;
            uint4 pk;
            pk.x = pack_bf16(a0, a1); pk.y = pack_bf16(a2, a3);
            pk.z = pack_bf16(a4, a5); pk.w = pack_bf16(a6, a7);
            *(uint4*)&sA[pnl * 4608 + rloc * 72 + cw] = pk;
        }
    }
    __syncthreads();

    // ---- phase 4: HMMA attn @ Wop^T ----
    float c[8][4];
#pragma unroll
    for (int b = 0; b < 8; b++)
#pragma unroll
        for (int j = 0; j < 4; j++) c[b][j] = 0.0f;

#pragma unroll
    for (int p = 0; p < 2; p++)
#pragma unroll
        for (int ks = 0; ks < 4; ks++) {
            uint32_t a0, a1, a2, a3;
            uint32_t aaddr = smem_u32(&sA[p * 4608 + (mt * 16 + (lane & 15)) * 72 +
                                          ks * 16 + (lane >> 4) * 8]);
            ldsm4(a0, a1, a2, a3, aaddr);
#pragma unroll
            for (int nb = 0; nb < 4; nb++) {
                uint32_t b0, b1, b2, b3;
                uint32_t baddr = smem_u32(&sB[p * 9216 +
                                              (nh * 64 + nb * 16 + (lane & 15)) * 72 +
                                              ks * 16 + (lane >> 4) * 8]);
                ldsm4(b0, b1, b2, b3, baddr);
                mma16816(c[nb * 2 + 0], a0, a1, a2, a3, b0, b2);
                mma16816(c[nb * 2 + 1], a0, a1, a2, a3, b1, b3);
            }
        }

    // ---- epilogue ----
    const int lrow0 = mt * 16 + qr;
    const int lrow1 = lrow0 + 8;
    const int r0 = row0 + lrow0;
    const int r1 = row0 + lrow1;
    float s0 = 0.f, q0 = 0.f, s1 = 0.f, q1 = 0.f;
#pragma unroll
    for (int b = 0; b < 8; b++) {
        int lcn = nh * 64 + b * 8 + qc;
        float2 rv0 = *(const float2*)&qsrc[(size_t)r0 * 128 + lcn];
        float2 rv1 = *(const float2*)&qsrc[(size_t)r1 * 128 + lcn];
        c[b][0] += s_bias[lcn]     + rv0.x;
        c[b][1] += s_bias[lcn + 1] + rv0.y;
        c[b][2] += s_bias[lcn]     + rv1.x;
        c[b][3] += s_bias[lcn + 1] + rv1.y;
        s0 += c[b][0] + c[b][1];  q0 += c[b][0] * c[b][0] + c[b][1] * c[b][1];
        s1 += c[b][2] + c[b][3];  q1 += c[b][2] * c[b][2] + c[b][3] * c[b][3];
    }
#pragma unroll
    for (int o = 1; o <= 2; o <<= 1) {
        s0 += __shfl_xor_sync(0xffffffffu, s0, o);
        q0 += __shfl_xor_sync(0xffffffffu, q0, o);
        s1 += __shfl_xor_sync(0xffffffffu, s1, o);
        q1 += __shfl_xor_sync(0xffffffffu, q1, o);
    }
    if ((lane & 3) == 0) {
        sLN[lrow0][nh] = make_float2(s0, q0);
        sLN[lrow1][nh] = make_float2(s1, q1);
    }
    __syncthreads();
    float2 t00 = sLN[lrow0][0], t01 = sLN[lrow0][1];
    float2 t10 = sLN[lrow1][0], t11 = sLN[lrow1][1];
    float m0 = (t00.x + t01.x) * (1.0f / 128.0f);
    float i0 = rsqrtf((t00.y + t01.y) * (1.0f / 128.0f) - m0 * m0 + 1e-5f);
    float m1 = (t10.x + t11.x) * (1.0f / 128.0f);
    float i1 = rsqrtf((t10.y + t11.y) * (1.0f / 128.0f) - m1 * m1 + 1e-5f);
#pragma unroll
    for (int b = 0; b < 8; b++) {
        int lcn = nh * 64 + b * 8 + qc;
        float2 o0, o1;
        o0.x = (c[b][0] - m0) * i0 * s_g[lcn]     + s_b[lcn];
        o0.y = (c[b][1] - m0) * i0 * s_g[lcn + 1] + s_b[lcn + 1];
        o1.x = (c[b][2] - m1) * i1 * s_g[lcn]     + s_b[lcn];
        o1.y = (c[b][3] - m1) * i1 * s_g[lcn + 1] + s_b[lcn + 1];
        *(float2*)&outp[(size_t)r0 * 128 + lcn] = o0;
        *(float2*)&outp[(size_t)r1 * 128 + lcn] = o1;
    }
}

// ---------------------------------------------------------------------------
// Fused FFN with register-resident hidden (R10 version: serial ks2, 16B staging)
// ---------------------------------------------------------------------------
#define FFN_SMEM (3 * 2 * 9216 * 2)
__global__ void __launch_bounds__(256, 2) ffn_fused(
    const float* __restrict__ qin, const __nv_bfloat16* __restrict__ W1,
    const float* __restrict__ b1, const __nv_bfloat16* __restrict__ W2,
    const float* __restrict__ b2, const float* __restrict__ lng,
    const float* __restrict__ lnb, float* __restrict__ outp)
{
    extern __shared__ __align__(16) uint8_t smraw[];
    __nv_bfloat16* sA  = (__nv_bfloat16*)smraw;
    __nv_bfloat16* sW1 = sA + 2 * 9216;
    __nv_bfloat16* sW2 = sW1 + 2 * 9216;
    __shared__ float s_b1[512], s_b2[128], s_g[128], s_b[128];

    const int tid  = threadIdx.x;
    const int wid  = tid >> 5;
    const int lane = tid & 31;
    const int row0 = blockIdx.x * 128;
    const int lr   = tid >> 4;
    const int lc4  = (tid & 15) * 4;
    const int wr   = tid >> 3;             // 0..31
    const int wc8  = (tid & 7) * 8;        // 0..56
    const int qr   = lane >> 2;
    const int qc   = (lane & 3) * 2;

    for (int i = tid; i < 512; i += 256) s_b1[i] = b1[i];
    if (tid < 128) { s_b2[tid] = b2[tid]; s_g[tid] = lng[tid]; s_b[tid] = lnb[tid]; }

#pragma unroll
    for (int p = 0; p < 2; p++)
#pragma unroll
        for (int i = 0; i < 8; i++) {
            int r = lr + i * 16;
            float4 v = *(const float4*)(qin + (size_t)(row0 + r) * 128 + p * 64 + lc4);
            uint2 pk; pk.x = pack_bf16(v.x, v.y); pk.y = pack_bf16(v.z, v.w);
            *(uint2*)&sA[p * 9216 + r * 72 + lc4] = pk;
        }
    __syncthreads();

    uint32_t aA[8][4];
#pragma unroll
    for (int p = 0; p < 2; p++)
#pragma unroll
        for (int ks = 0; ks < 4; ks++) {
            uint32_t addr = smem_u32(&sA[p * 9216 + (wid * 16 + (lane & 15)) * 72 +
                                         ks * 16 + (lane >> 4) * 8]);
            ldsm4(aA[p * 4 + ks][0], aA[p * 4 + ks][1],
                  aA[p * 4 + ks][2], aA[p * 4 + ks][3], addr);
        }

    float co[16][4];
#pragma unroll
    for (int b = 0; b < 16; b++)
#pragma unroll
        for (int j = 0; j < 4; j++) co[b][j] = 0.0f;

    for (int j = 0; j < 4; j++) {
        __syncthreads();
#pragma unroll
        for (int p = 0; p < 2; p++)
#pragma unroll
            for (int i = 0; i < 4; i++) {
                int r = wr + i * 32;
                uint4 w1 = *(const uint4*)(W1 + (size_t)(j * 128 + r) * 128 + p * 64 + wc8);
                *(uint4*)&sW1[p * 9216 + r * 72 + wc8] = w1;
                uint4 w2 = *(const uint4*)(W2 + (size_t)r * 512 + j * 128 + p * 64 + wc8);
                *(uint4*)&sW2[p * 9216 + r * 72 + wc8] = w2;
            }
        __syncthreads();

#pragma unroll
        for (int ks2 = 0; ks2 < 8; ks2++) {
            float hh0[4] = {0.f, 0.f, 0.f, 0.f};
            float hh1[4] = {0.f, 0.f, 0.f, 0.f};
#pragma unroll
            for (int p = 0; p < 2; p++)
#pragma unroll
                for (int ks = 0; ks < 4; ks++) {
                    uint32_t b0, b1r, b2r, b3;
                    uint32_t baddr = smem_u32(&sW1[p * 9216 +
                                                   (ks2 * 16 + (lane & 15)) * 72 +
                                                   ks * 16 + (lane >> 4) * 8]);
                    ldsm4(b0, b1r, b2r, b3, baddr);
                    mma16816(hh0, aA[p * 4 + ks][0], aA[p * 4 + ks][1],
                             aA[p * 4 + ks][2], aA[p * 4 + ks][3], b0, b2r);
                    mma16816(hh1, aA[p * 4 + ks][0], aA[p * 4 + ks][1],
                             aA[p * 4 + ks][2], aA[p * 4 + ks][3], b1r, b3);
                }
            int hc = j * 128 + ks2 * 16;
            float v00 = fmaxf(hh0[0] + s_b1[hc + qc],     0.0f);
            float v01 = fmaxf(hh0[1] + s_b1[hc + qc + 1], 0.0f);
            float v02 = fmaxf(hh0[2] + s_b1[hc + qc],     0.0f);
            float v03 = fmaxf(hh0[3] + s_b1[hc + qc + 1], 0.0f);
            float v10 = fmaxf(hh1[0] + s_b1[hc + 8 + qc],     0.0f);
            float v11 = fmaxf(hh1[1] + s_b1[hc + 8 + qc + 1], 0.0f);
            float v12 = fmaxf(hh1[2] + s_b1[hc + 8 + qc],     0.0f);
            float v13 = fmaxf(hh1[3] + s_b1[hc + 8 + qc + 1], 0.0f);
            uint32_t fa0 = pack_bf16(v00, v01);
            uint32_t fa1 = pack_bf16(v02, v03);
            uint32_t fa2 = pack_bf16(v10, v11);
            uint32_t fa3 = pack_bf16(v12, v13);
            int p2 = ks2 >> 2, kk = ks2 & 3;
#pragma unroll
            for (int nb = 0; nb < 8; nb++) {
                uint32_t b0, b1r, b2r, b3;
                uint32_t baddr = smem_u32(&sW2[p2 * 9216 +
                                               (nb * 16 + (lane & 15)) * 72 +
                                               kk * 16 + (lane >> 4) * 8]);
                ldsm4(b0, b1r, b2r, b3, baddr);
                mma16816(co[nb * 2 + 0], fa0, fa1, fa2, fa3, b0, b2r);
                mma16816(co[nb * 2 + 1], fa0, fa1, fa2, fa3, b1r, b3);
            }
        }
    }

    const int r0 = row0 + wid * 16 + qr;
    const int r1 = r0 + 8;
    float s0 = 0.f, q0 = 0.f, s1 = 0.f, q1 = 0.f;
#pragma unroll
    for (int b = 0; b < 16; b++) {
        int lcn = b * 8 + qc;
        float2 rv0 = *(const float2*)&qin[(size_t)r0 * 128 + lcn];
        float2 rv1 = *(const float2*)&qin[(size_t)r1 * 128 + lcn];
        co[b][0] += s_b2[lcn]     + rv0.x;
        co[b][1] += s_b2[lcn + 1] + rv0.y;
        co[b][2] += s_b2[lcn]     + rv1.x;
        co[b][3] += s_b2[lcn + 1] + rv1.y;
        s0 += co[b][0] + co[b][1];  q0 += co[b][0] * co[b][0] + co[b][1] * co[b][1];
        s1 += co[b][2] + co[b][3];  q1 += co[b][2] * co[b][2] + co[b][3] * co[b][3];
    }
#pragma unroll
    for (int o = 1; o <= 2; o <<= 1) {
        s0 += __shfl_xor_sync(0xffffffffu, s0, o);
        q0 += __shfl_xor_sync(0xffffffffu, q0, o);
        s1 += __shfl_xor_sync(0xffffffffu, s1, o);
        q1 += __shfl_xor_sync(0xffffffffu, q1, o);
    }
    float m0 = s0 * (1.0f / 128.0f);
    float i0 = rsqrtf(q0 * (1.0f / 128.0f) - m0 * m0 + 1e-5f);
    float m1 = s1 * (1.0f / 128.0f);
    float i1 = rsqrtf(q1 * (1.0f / 128.0f) - m1 * m1 + 1e-5f);
#pragma unroll
    for (int b = 0; b < 16; b++) {
        int lcn = b * 8 + qc;
        float2 o0, o1;
        o0.x = (co[b][0] - m0) * i0 * s_g[lcn]     + s_b[lcn];
        o0.y = (co[b][1] - m0) * i0 * s_g[lcn + 1] + s_b[lcn + 1];
        o1.x = (co[b][2] - m1) * i1 * s_g[lcn]     + s_b[lcn];
        o1.y = (co[b][3] - m1) * i1 * s_g[lcn + 1] + s_b[lcn + 1];
        *(float2*)&outp[(size_t)r0 * 128 + lcn] = o0;
        *(float2*)&outp[(size_t)r1 * 128 + lcn] = o1;
    }
}

// ---------------------------------------------------------------------------
extern "C" void kernel_launch(void* const* d_in, const int* in_sizes, int n_in,
                              void* d_out, int out_size)
{
    const float* query = (const float*)d_in[0];
    const float* src   = (const float*)d_in[1];
    const float* pos   = (const float*)d_in[2];
    const float* so_w  = (const float*)d_in[3];
    const float* so_b  = (const float*)d_in[4];
    const float* aw_w  = (const float*)d_in[5];
    const float* aw_b  = (const float*)d_in[6];
    const float* vp_w  = (const float*)d_in[7];
    const float* vp_b  = (const float*)d_in[8];
    const float* op_w  = (const float*)d_in[9];
    const float* op_b  = (const float*)d_in[10];
    const float* ln1_g = (const float*)d_in[11];
    const float* ln1_b = (const float*)d_in[12];
    const float* l1_w  = (const float*)d_in[13];
    const float* l1_b  = (const float*)d_in[14];
    const float* l2_w  = (const float*)d_in[15];
    const float* l2_b  = (const float*)d_in[16];
    const float* ln2_g = (const float*)d_in[17];
    const float* ln2_b = (const float*)d_in[18];

    float* qbuf;
    __nv_bfloat16 *vbuf, *wbuf, *wsobuf;
    cudaGetSymbolAddress((void**)&qbuf, g_q);
    cudaGetSymbolAddress((void**)&vbuf, g_value);
    cudaGetSymbolAddress((void**)&wbuf, g_wb);
    cudaGetSymbolAddress((void**)&wsobuf, g_wso);

    cudaFuncSetAttribute(ffn_fused, cudaFuncAttributeMaxDynamicSharedMemorySize, FFN_SMEM);
    cudaFuncSetAttribute(attn_fused, cudaFuncAttributeMaxDynamicSharedMemorySize, ATT_SMEM);
    cudaFuncSetAttribute(gemm_vp, cudaFuncAttributeMaxDynamicSharedMemorySize, VP_SMEM);

    prep_weights<<<(PREP_TOTAL + 255) / 256, 256>>>(vp_w, op_w, l1_w, l2_w, so_w, aw_w);
    gemm_vp<<<NTOK / 128, 256, VP_SMEM>>>(src, vp_b);

    for (int l = 0; l < 2; l++) {
        const __nv_bfloat16* wb = wbuf + (size_t)l * WB_LAYER;
        const float* qsrc = (l == 0) ? query : qbuf;
        float* ffn_out = (l == 0) ? qbuf : (float*)d_out;
        attn_fused<<<NTOK / 64, 256, ATT_SMEM>>>(
            vbuf + (size_t)l * NTOK * DM, wb + WB_OP, op_b + l * DM,
            so_b + l * 32, aw_b + l * 16, qsrc, pos,
            wsobuf + (size_t)l * 8192, ln1_g + l * DM, ln1_b + l * DM, qbuf);
        ffn_fused<<<NTOK / 128, 256, FFN_SMEM>>>(
            qbuf, wb + WB_L1, l1_b + l * FFD, wb + WB_L2, l2_b + l * DM,
            ln2_g + l * DM, ln2_b + l * DM, ffn_out);
    }
}

// round 16
// speedup vs baseline: 1.0145x; 1.0145x over previous
#include <cuda_runtime.h>
#include <cuda_bf16.h>
#include <math.h>
#include <stdint.h>

// Problem constants
#define NTOK 65536   // B * Lq = 4 * 16384
#define LQ   16384
#define DM   128
#define NHH  4
#define NPP  4
#define HDD  32
#define FFD  512
#define GW   128
#define GH   128

// ---------------- device scratch ----------------
__device__ __align__(16) float g_q[NTOK * DM];                     // running query
__device__ __align__(16) __nv_bfloat16 g_value[2 * NTOK * DM];     // value (bf16, both layers)
// bf16 transposed weights: per layer [vp 128x128][op 128x128][l1 512x128][l2 128x512]
#define WB_LAYER 163840
#define WB_VP 0
#define WB_OP 16384
#define WB_L1 32768
#define WB_L2 98304
__device__ __align__(16) __nv_bfloat16 g_wb[2 * WB_LAYER];
// combined sampling-param weights: per layer [64 rows][128] bf16
__device__ __align__(16) __nv_bfloat16 g_wso[2 * 64 * 128];

// ---------------- helpers ----------------
__device__ __forceinline__ uint32_t smem_u32(const void* p) {
    uint32_t a;
    asm("{ .reg .u64 t; cvta.to.shared.u64 t, %1; cvt.u32.u64 %0, t; }" : "=r"(a) : "l"(p));
    return a;
}
__device__ __forceinline__ uint32_t pack_bf16(float x, float y) {
    __nv_bfloat162 h = __floats2bfloat162_rn(x, y);
    return *(uint32_t*)&h;
}
__device__ __forceinline__ float2 unpk(uint32_t u) {
    return __bfloat1622float2(*(__nv_bfloat162*)&u);
}
__device__ __forceinline__ void ldsm4(uint32_t& r0, uint32_t& r1, uint32_t& r2, uint32_t& r3,
                                      uint32_t addr) {
    asm volatile("ldmatrix.sync.aligned.m8n8.x4.shared.b16 {%0,%1,%2,%3}, [%4];"
                 : "=r"(r0), "=r"(r1), "=r"(r2), "=r"(r3) : "r"(addr));
}
__device__ __forceinline__ void mma16816(float* c, uint32_t a0, uint32_t a1, uint32_t a2,
                                         uint32_t a3, uint32_t b0, uint32_t b1) {
    asm volatile(
        "mma.sync.aligned.m16n8k16.row.col.f32.bf16.bf16.f32 "
        "{%0,%1,%2,%3}, {%4,%5,%6,%7}, {%8,%9}, {%0,%1,%2,%3};"
        : "+f"(c[0]), "+f"(c[1]), "+f"(c[2]), "+f"(c[3])
        : "r"(a0), "r"(a1), "r"(a2), "r"(a3), "r"(b0), "r"(b1));
}

// ---------------------------------------------------------------------------
// Shared vp tile body: out_value[row0..row0+127] = src @ vp_w^T + bias (bf16).
// Uses caller-provided smem (needs 4*9216*2 bytes) and a 128-float bias array.
// Whole-block execution (uniform __syncthreads).
// ---------------------------------------------------------------------------
__device__ __forceinline__ void vp_tile_body(
    const float* __restrict__ src, const float* __restrict__ vp_b_layer,
    int layer, int row0, uint8_t* smraw, float* s_bias)
{
    __nv_bfloat16* sA = (__nv_bfloat16*)smraw;   // 2 x 9216
    __nv_bfloat16* sB = sA + 2 * 9216;           // 2 x 9216

    const int tid  = threadIdx.x;
    const int wid  = tid >> 5;
    const int lane = tid & 31;
    const int lr   = tid >> 4;
    const int lc4  = (tid & 15) * 4;
    const int wr   = tid >> 3;
    const int wc8  = (tid & 7) * 8;

    const __nv_bfloat16* Wb = g_wb + (size_t)layer * WB_LAYER + WB_VP;
    __nv_bfloat16* outp = g_value + (size_t)layer * NTOK * DM;

    if (tid < 128) s_bias[tid] = vp_b_layer[tid];

    // stage src tile (fp32 -> bf16) and weights
#pragma unroll
    for (int p = 0; p < 2; p++) {
#pragma unroll
        for (int i = 0; i < 8; i++) {
            int r = lr + i * 16;
            float4 v = *(const float4*)(src + (size_t)(row0 + r) * 128 + p * 64 + lc4);
            uint2 pk; pk.x = pack_bf16(v.x, v.y); pk.y = pack_bf16(v.z, v.w);
            *(uint2*)&sA[p * 9216 + r * 72 + lc4] = pk;
        }
#pragma unroll
        for (int i = 0; i < 4; i++) {
            int r = wr + i * 32;
            uint4 w = *(const uint4*)(Wb + (size_t)r * 128 + p * 64 + wc8);
            *(uint4*)&sB[p * 9216 + r * 72 + wc8] = w;
        }
    }
    __syncthreads();

    float c[16][4];
#pragma unroll
    for (int b = 0; b < 16; b++)
#pragma unroll
        for (int j = 0; j < 4; j++) c[b][j] = 0.0f;
#pragma unroll
    for (int p = 0; p < 2; p++)
#pragma unroll
        for (int ks = 0; ks < 4; ks++) {
            uint32_t a0, a1, a2, a3;
            uint32_t aaddr = smem_u32(&sA[p * 9216 + (wid * 16 + (lane & 15)) * 72 +
                                          ks * 16 + (lane >> 4) * 8]);
            ldsm4(a0, a1, a2, a3, aaddr);
#pragma unroll
            for (int nb = 0; nb < 8; nb++) {
                uint32_t b0, b1, b2, b3;
                uint32_t baddr = smem_u32(&sB[p * 9216 + (nb * 16 + (lane & 15)) * 72 +
                                              ks * 16 + (lane >> 4) * 8]);
                ldsm4(b0, b1, b2, b3, baddr);
                mma16816(c[nb * 2 + 0], a0, a1, a2, a3, b0, b2);
                mma16816(c[nb * 2 + 1], a0, a1, a2, a3, b1, b3);
            }
        }

    const int qr = lane >> 2;
    const int qc = (lane & 3) * 2;
    const int r0 = row0 + wid * 16 + qr;
    const int r1 = r0 + 8;
#pragma unroll
    for (int b = 0; b < 16; b++) {
        int lcn = b * 8 + qc;
        *(uint32_t*)&outp[(size_t)r0 * 128 + lcn] =
            pack_bf16(c[b][0] + s_bias[lcn], c[b][1] + s_bias[lcn + 1]);
        *(uint32_t*)&outp[(size_t)r1 * 128 + lcn] =
            pack_bf16(c[b][2] + s_bias[lcn], c[b][3] + s_bias[lcn + 1]);
    }
}

// ---------------------------------------------------------------------------
// Weight prep: W[K][N] fp32 -> Wb[N][K] bf16 for all matrices + so/aw combo.
// ---------------------------------------------------------------------------
#define PREP_TOTAL (2 * WB_LAYER + 2 * 64 * 128)
__global__ void __launch_bounds__(256) prep_weights(
    const float* __restrict__ vp_w, const float* __restrict__ op_w,
    const float* __restrict__ l1_w, const float* __restrict__ l2_w,
    const float* __restrict__ so_w, const float* __restrict__ aw_w)
{
    int idx = blockIdx.x * 256 + threadIdx.x;
    if (idx >= PREP_TOTAL) return;
    if (idx < 2 * WB_LAYER) {
        int l = idx / WB_LAYER;
        int r = idx % WB_LAYER;
        const float* W; int K, N, off;
        if (r < 16384)       { W = vp_w + l * 16384; K = 128; N = 128; off = WB_VP; }
        else if (r < 32768)  { W = op_w + l * 16384; r -= 16384; K = 128; N = 128; off = WB_OP; }
        else if (r < 98304)  { W = l1_w + l * 65536; r -= 32768; K = 128; N = 512; off = WB_L1; }
        else                 { W = l2_w + l * 65536; r -= 98304; K = 512; N = 128; off = WB_L2; }
        int n = r / K, k = r % K;
        g_wb[l * WB_LAYER + off + r] = __float2bfloat16(W[k * N + n]);
    } else {
        int r2 = idx - 2 * WB_LAYER;     // 0..16383
        int l = r2 / 8192; r2 -= l * 8192;
        int n = r2 / 128, k = r2 % 128;
        float v = 0.0f;
        if (n < 32)      v = so_w[(size_t)l * 128 * 32 + k * 32 + n];
        else if (n < 48) v = aw_w[(size_t)l * 128 * 16 + k * 16 + (n - 32)];
        g_wso[(size_t)l * 8192 + n * 128 + k] = __float2bfloat16(v);
    }
}

// ---------------------------------------------------------------------------
// Value projection, LAYER 0 only (layer 1 is co-scheduled with ffn-l0).
// ---------------------------------------------------------------------------
#define VP_SMEM (4 * 9216 * 2)
__global__ void __launch_bounds__(256, 2) gemm_vp(
    const float* __restrict__ src, const float* __restrict__ vp_b)
{
    extern __shared__ __align__(16) uint8_t smraw[];
    __shared__ float s_bias[128];
    vp_tile_body(src, vp_b, 0, blockIdx.x * 128, smraw, s_bias);
}

// ---------------------------------------------------------------------------
// Fully fused deformable attention with overlaid phase buffers (R12, 319.9us).
// ---------------------------------------------------------------------------
#define ATT_SMEM (18432 + 36864 + 17408)
__global__ void __launch_bounds__(256, 3) attn_fused(
    const __nv_bfloat16* __restrict__ value, const __nv_bfloat16* __restrict__ Wop,
    const float* __restrict__ op_bias, const float* __restrict__ so_b,
    const float* __restrict__ aw_b, const float* __restrict__ qsrc,
    const float* __restrict__ pos, const __nv_bfloat16* __restrict__ Wso,
    const float* __restrict__ lng, const float* __restrict__ lnb,
    float* __restrict__ outp)
{
    extern __shared__ __align__(16) uint8_t smraw[];
    __nv_bfloat16* sA  = (__nv_bfloat16*)smraw;      // 2 panels x (64 x 72)
    __nv_bfloat16* sB  = sA + 2 * 4608;              // 2 panels x (128 x 72)
    uint8_t* region = (uint8_t*)(sB + 2 * 9216);     // 17408B overlay
    __nv_bfloat16* sWc = (__nv_bfloat16*)region;     // 2 panels x (48 x 72)
    float*  sOuts = (float*)region;                  // 64 x 68
    float2* sLoc  = (float2*)region;                 // [64][16] (px,py)  (8192B)
    float*  sAw   = (float*)(region + 8192);         // [64][16]          (4096B)
    __shared__ float s_bias[128], s_g[128], s_b[128], s_pb[64];
    __shared__ float2 sLN[64][2];

    const int tid  = threadIdx.x;
    const int wid  = tid >> 5;
    const int lane = tid & 31;
    const int row0 = blockIdx.x * 64;
    const int batch = row0 >> 14;
    const int lr   = tid >> 4;
    const int lc4  = (tid & 15) * 4;
    const int wr   = tid >> 3;             // 0..31
    const int wc8  = (tid & 7) * 8;        // 0..56

    if (tid < 128) { s_bias[tid] = op_bias[tid]; s_g[tid] = lng[tid]; s_b[tid] = lnb[tid]; }
    else if (tid < 192) {
        int o = tid - 128;
        s_pb[o] = (o < 32) ? so_b[o] : ((o < 48) ? aw_b[o - 32] : 0.0f);
    }

    // ---- phase 0: stage qin (bf16), Wso (48 rows), op weights ----
#pragma unroll
    for (int p = 0; p < 2; p++)
#pragma unroll
        for (int i = 0; i < 4; i++) {
            int r = lr + i * 16;
            int col = p * 64 + lc4;
            float4 qv = *(const float4*)(qsrc + (size_t)(row0 + r) * 128 + col);
            float4 pv = *(const float4*)(pos  + (size_t)(row0 + r) * 128 + col);
            uint2 pk;
            pk.x = pack_bf16(qv.x + pv.x, qv.y + pv.y);
            pk.y = pack_bf16(qv.z + pv.z, qv.w + pv.w);
            *(uint2*)&sA[p * 4608 + r * 72 + lc4] = pk;
        }
#pragma unroll
    for (int p = 0; p < 2; p++) {
#pragma unroll
        for (int i = 0; i < 2; i++) {
            int r = wr + i * 32;
            if (r < 48) {
                uint4 w = *(const uint4*)(Wso + (size_t)r * 128 + p * 64 + wc8);
                *(uint4*)&sWc[p * 3456 + r * 72 + wc8] = w;
            }
        }
#pragma unroll
        for (int i = 0; i < 4; i++) {
            int r = wr + i * 32;
            uint4 w = *(const uint4*)(Wop + (size_t)r * 128 + p * 64 + wc8);
            *(uint4*)&sB[p * 9216 + r * 72 + wc8] = w;
        }
    }
    __syncthreads();

    const int mt = wid >> 1;
    const int nh = wid & 1;
    const int qr = lane >> 2;
    const int qc = (lane & 3) * 2;

    // ---- phase 1: params HMMA ----
    {
        float cp[4][4];
#pragma unroll
        for (int b = 0; b < 4; b++)
#pragma unroll
            for (int j = 0; j < 4; j++) cp[b][j] = 0.0f;
        const int nbmax = (nh == 0) ? 2 : 1;
#pragma unroll
        for (int p = 0; p < 2; p++)
#pragma unroll
            for (int ks = 0; ks < 4; ks++) {
                uint32_t a0, a1, a2, a3;
                uint32_t aaddr = smem_u32(&sA[p * 4608 + (mt * 16 + (lane & 15)) * 72 +
                                              ks * 16 + (lane >> 4) * 8]);
                ldsm4(a0, a1, a2, a3, aaddr);
                for (int nb = 0; nb < nbmax; nb++) {
                    uint32_t b0, b1, b2, b3;
                    uint32_t baddr = smem_u32(&sWc[p * 3456 +
                                                   (nh * 32 + nb * 16 + (lane & 15)) * 72 +
                                                   ks * 16 + (lane >> 4) * 8]);
                    ldsm4(b0, b1, b2, b3, baddr);
                    mma16816(cp[nb * 2 + 0], a0, a1, a2, a3, b0, b2);
                    mma16816(cp[nb * 2 + 1], a0, a1, a2, a3, b1, b3);
                }
            }
        __syncthreads();
        const int lrow0 = mt * 16 + qr, lrow1 = lrow0 + 8;
        for (int b = 0; b < 2 * nbmax; b++) {
            int col = nh * 32 + b * 8 + qc;
            sOuts[lrow0 * 68 + col]     = cp[b][0] + s_pb[col];
            sOuts[lrow0 * 68 + col + 1] = cp[b][1] + s_pb[col + 1];
            sOuts[lrow1 * 68 + col]     = cp[b][2] + s_pb[col];
            sOuts[lrow1 * 68 + col + 1] = cp[b][3] + s_pb[col + 1];
        }
    }
    __syncthreads();

    // ---- phase 2: softmax + pixel locations ----
    {
        const int tk = tid >> 2, h = tid & 3;
        const int gq = row0 + tk;
        const float* ob = &sOuts[tk * 68];
        float offs[8];
#pragma unroll
        for (int i = 0; i < 8; i++) offs[i] = ob[h * 8 + i];
        float lg0 = ob[32 + h * 4 + 0];
        float lg1 = ob[32 + h * 4 + 1];
        float lg2 = ob[32 + h * 4 + 2];
        float lg3 = ob[32 + h * 4 + 3];
        __syncthreads();
        float m = fmaxf(fmaxf(lg0, lg1), fmaxf(lg2, lg3));
        float e0 = expf(lg0 - m), e1 = expf(lg1 - m), e2 = expf(lg2 - m), e3 = expf(lg3 - m);
        float inv = 1.0f / (e0 + e1 + e2 + e3);
        float jx = (float)(gq & (GW - 1));
        float iy = (float)((gq >> 7) & (GH - 1));
#pragma unroll
        for (int p = 0; p < 4; p++)
            sLoc[tk * 16 + h * 4 + p] = make_float2(jx + offs[p * 2], iy + offs[p * 2 + 1]);
        sAw[tk * 16 + h * 4 + 0] = e0 * inv;
        sAw[tk * 16 + h * 4 + 1] = e1 * inv;
        sAw[tk * 16 + h * 4 + 2] = e2 * inv;
        sAw[tk * 16 + h * 4 + 3] = e3 * inv;
    }
    __syncthreads();

    // ---- phase 3: bilinear sampling into sA ----
    {
        const int half = lane >> 4;
        const int l16  = lane & 15;
        const int h    = l16 >> 2;
        const int cg   = l16 & 3;
        const __nv_bfloat16* vplane = value + (size_t)batch * LQ * DM + h * HDD + cg * 8;

#pragma unroll
        for (int it = 0; it < 4; it++) {
            const int rloc = wid * 8 + it * 2 + half;
            const int pbase = rloc * 16 + h * 4;

            float a0 = 0.f, a1 = 0.f, a2 = 0.f, a3 = 0.f;
            float a4 = 0.f, a5 = 0.f, a6 = 0.f, a7 = 0.f;
#pragma unroll
            for (int p = 0; p < 4; p++) {
                float2 lp = sLoc[pbase + p];
                float aw = sAw[pbase + p];
                float px = lp.x, py = lp.y;
                float fx = floorf(px), fy = floorf(py);
                int x0 = (int)fx, y0 = (int)fy;
                float wx = px - fx, wy = py - fy;
                float w00 = (1.0f - wx) * (1.0f - wy) * aw;
                float w10 = wx * (1.0f - wy) * aw;
                float w01 = (1.0f - wx) * wy * aw;
                float w11 = wx * wy * aw;
                int x1 = x0 + 1, y1 = y0 + 1;
                bool bx0 = (x0 >= 0) & (x0 < GW);
                bool bx1 = (x1 >= 0) & (x1 < GW);
                bool by0 = (y0 >= 0) & (y0 < GH);
                bool by1 = (y1 >= 0) & (y1 < GH);
#define GATHER(wgt, xx, yy) do { \
                    uint4 v = *(const uint4*)&vplane[((size_t)(yy) * GW + (xx)) * DM]; \
                    float2 f0 = unpk(v.x), f1 = unpk(v.y), f2 = unpk(v.z), f3 = unpk(v.w); \
                    a0 += (wgt) * f0.x; a1 += (wgt) * f0.y; \
                    a2 += (wgt) * f1.x; a3 += (wgt) * f1.y; \
                    a4 += (wgt) * f2.x; a5 += (wgt) * f2.y; \
                    a6 += (wgt) * f3.x; a7 += (wgt) * f3.y; \
                } while (0)
                if (bx0 & by0) GATHER(w00, x0, y0);
                if (bx1 & by0) GATHER(w10, x1, y0);
                if (bx0 & by1) GATHER(w01, x0, y1);
                if (bx1 & by1) GATHER(w11, x1, y1);
#undef GATHER
            }
            const int c   = h * HDD + cg * 8;
            const int pnl = c >> 6, cw = c & 63;
            uint4 pk;
            pk.x = pack_bf16(a0, a1); pk.y = pack_bf16(a2, a3);
            pk.z = pack_bf16(a4, a5); pk.w = pack_bf16(a6, a7);
            *(uint4*)&sA[pnl * 4608 + rloc * 72 + cw] = pk;
        }
    }
    __syncthreads();

    // ---- phase 4: HMMA attn @ Wop^T ----
    float c[8][4];
#pragma unroll
    for (int b = 0; b < 8; b++)
#pragma unroll
        for (int j = 0; j < 4; j++) c[b][j] = 0.0f;

#pragma unroll
    for (int p = 0; p < 2; p++)
#pragma unroll
        for (int ks = 0; ks < 4; ks++) {
            uint32_t a0, a1, a2, a3;
            uint32_t aaddr = smem_u32(&sA[p * 4608 + (mt * 16 + (lane & 15)) * 72 +
                                          ks * 16 + (lane >> 4) * 8]);
            ldsm4(a0, a1, a2, a3, aaddr);
#pragma unroll
            for (int nb = 0; nb < 4; nb++) {
                uint32_t b0, b1, b2, b3;
                uint32_t baddr = smem_u32(&sB[p * 9216 +
                                              (nh * 64 + nb * 16 + (lane & 15)) * 72 +
                                              ks * 16 + (lane >> 4) * 8]);
                ldsm4(b0, b1, b2, b3, baddr);
                mma16816(c[nb * 2 + 0], a0, a1, a2, a3, b0, b2);
                mma16816(c[nb * 2 + 1], a0, a1, a2, a3, b1, b3);
            }
        }

    // ---- epilogue ----
    const int lrow0 = mt * 16 + qr;
    const int lrow1 = lrow0 + 8;
    const int r0 = row0 + lrow0;
    const int r1 = row0 + lrow1;
    float s0 = 0.f, q0 = 0.f, s1 = 0.f, q1 = 0.f;
#pragma unroll
    for (int b = 0; b < 8; b++) {
        int lcn = nh * 64 + b * 8 + qc;
        float2 rv0 = *(const float2*)&qsrc[(size_t)r0 * 128 + lcn];
        float2 rv1 = *(const float2*)&qsrc[(size_t)r1 * 128 + lcn];
        c[b][0] += s_bias[lcn]     + rv0.x;
        c[b][1] += s_bias[lcn + 1] + rv0.y;
        c[b][2] += s_bias[lcn]     + rv1.x;
        c[b][3] += s_bias[lcn + 1] + rv1.y;
        s0 += c[b][0] + c[b][1];  q0 += c[b][0] * c[b][0] + c[b][1] * c[b][1];
        s1 += c[b][2] + c[b][3];  q1 += c[b][2] * c[b][2] + c[b][3] * c[b][3];
    }
#pragma unroll
    for (int o = 1; o <= 2; o <<= 1) {
        s0 += __shfl_xor_sync(0xffffffffu, s0, o);
        q0 += __shfl_xor_sync(0xffffffffu, q0, o);
        s1 += __shfl_xor_sync(0xffffffffu, s1, o);
        q1 += __shfl_xor_sync(0xffffffffu, q1, o);
    }
    if ((lane & 3) == 0) {
        sLN[lrow0][nh] = make_float2(s0, q0);
        sLN[lrow1][nh] = make_float2(s1, q1);
    }
    __syncthreads();
    float2 t00 = sLN[lrow0][0], t01 = sLN[lrow0][1];
    float2 t10 = sLN[lrow1][0], t11 = sLN[lrow1][1];
    float m0 = (t00.x + t01.x) * (1.0f / 128.0f);
    float i0 = rsqrtf((t00.y + t01.y) * (1.0f / 128.0f) - m0 * m0 + 1e-5f);
    float m1 = (t10.x + t11.x) * (1.0f / 128.0f);
    float i1 = rsqrtf((t10.y + t11.y) * (1.0f / 128.0f) - m1 * m1 + 1e-5f);
#pragma unroll
    for (int b = 0; b < 8; b++) {
        int lcn = nh * 64 + b * 8 + qc;
        float2 o0, o1;
        o0.x = (c[b][0] - m0) * i0 * s_g[lcn]     + s_b[lcn];
        o0.y = (c[b][1] - m0) * i0 * s_g[lcn + 1] + s_b[lcn + 1];
        o1.x = (c[b][2] - m1) * i1 * s_g[lcn]     + s_b[lcn];
        o1.y = (c[b][3] - m1) * i1 * s_g[lcn + 1] + s_b[lcn + 1];
        *(float2*)&outp[(size_t)r0 * 128 + lcn] = o0;
        *(float2*)&outp[(size_t)r1 * 128 + lcn] = o1;
    }
}

// ---------------------------------------------------------------------------
// Fused FFN with register-resident hidden. WITH_VP=true appends 512 CTAs that
// execute the layer-1 value projection (fills ffn's tail wave).
// ---------------------------------------------------------------------------
#define FFN_SMEM (3 * 2 * 9216 * 2)
#define FFN_GRID (NTOK / 128)
template<bool WITH_VP>
__global__ void __launch_bounds__(256, 2) ffn_fused(
    const float* __restrict__ qin, const __nv_bfloat16* __restrict__ W1,
    const float* __restrict__ b1, const __nv_bfloat16* __restrict__ W2,
    const float* __restrict__ b2, const float* __restrict__ lng,
    const float* __restrict__ lnb, float* __restrict__ outp,
    const float* __restrict__ src, const float* __restrict__ vp_b)
{
    extern __shared__ __align__(16) uint8_t smraw[];
    __shared__ float s_b1[512], s_b2[128], s_g[128], s_b[128];

    if (WITH_VP && blockIdx.x >= FFN_GRID) {
        // layer-1 value projection tile (uses first 73.7KB of smraw, s_b2 bias)
        vp_tile_body(src, vp_b + 128, 1, (blockIdx.x - FFN_GRID) * 128, smraw, s_b2);
        return;
    }

    __nv_bfloat16* sA  = (__nv_bfloat16*)smraw;
    __nv_bfloat16* sW1 = sA + 2 * 9216;
    __nv_bfloat16* sW2 = sW1 + 2 * 9216;

    const int tid  = threadIdx.x;
    const int wid  = tid >> 5;
    const int lane = tid & 31;
    const int row0 = blockIdx.x * 128;
    const int lr   = tid >> 4;
    const int lc4  = (tid & 15) * 4;
    const int wr   = tid >> 3;             // 0..31
    const int wc8  = (tid & 7) * 8;        // 0..56
    const int qr   = lane >> 2;
    const int qc   = (lane & 3) * 2;

    for (int i = tid; i < 512; i += 256) s_b1[i] = b1[i];
    if (tid < 128) { s_b2[tid] = b2[tid]; s_g[tid] = lng[tid]; s_b[tid] = lnb[tid]; }

#pragma unroll
    for (int p = 0; p < 2; p++)
#pragma unroll
        for (int i = 0; i < 8; i++) {
            int r = lr + i * 16;
            float4 v = *(const float4*)(qin + (size_t)(row0 + r) * 128 + p * 64 + lc4);
            uint2 pk; pk.x = pack_bf16(v.x, v.y); pk.y = pack_bf16(v.z, v.w);
            *(uint2*)&sA[p * 9216 + r * 72 + lc4] = pk;
        }
    __syncthreads();

    uint32_t aA[8][4];
#pragma unroll
    for (int p = 0; p < 2; p++)
#pragma unroll
        for (int ks = 0; ks < 4; ks++) {
            uint32_t addr = smem_u32(&sA[p * 9216 + (wid * 16 + (lane & 15)) * 72 +
                                         ks * 16 + (lane >> 4) * 8]);
            ldsm4(aA[p * 4 + ks][0], aA[p * 4 + ks][1],
                  aA[p * 4 + ks][2], aA[p * 4 + ks][3], addr);
        }

    float co[16][4];
#pragma unroll
    for (int b = 0; b < 16; b++)
#pragma unroll
        for (int j = 0; j < 4; j++) co[b][j] = 0.0f;

    for (int j = 0; j < 4; j++) {
        __syncthreads();
#pragma unroll
        for (int p = 0; p < 2; p++)
#pragma unroll
            for (int i = 0; i < 4; i++) {
                int r = wr + i * 32;
                uint4 w1 = *(const uint4*)(W1 + (size_t)(j * 128 + r) * 128 + p * 64 + wc8);
                *(uint4*)&sW1[p * 9216 + r * 72 + wc8] = w1;
                uint4 w2 = *(const uint4*)(W2 + (size_t)r * 512 + j * 128 + p * 64 + wc8);
                *(uint4*)&sW2[p * 9216 + r * 72 + wc8] = w2;
            }
        __syncthreads();

#pragma unroll
        for (int ks2 = 0; ks2 < 8; ks2++) {
            float hh0[4] = {0.f, 0.f, 0.f, 0.f};
            float hh1[4] = {0.f, 0.f, 0.f, 0.f};
#pragma unroll
            for (int p = 0; p < 2; p++)
#pragma unroll
                for (int ks = 0; ks < 4; ks++) {
                    uint32_t b0, b1r, b2r, b3;
                    uint32_t baddr = smem_u32(&sW1[p * 9216 +
                                                   (ks2 * 16 + (lane & 15)) * 72 +
                                                   ks * 16 + (lane >> 4) * 8]);
                    ldsm4(b0, b1r, b2r, b3, baddr);
                    mma16816(hh0, aA[p * 4 + ks][0], aA[p * 4 + ks][1],
                             aA[p * 4 + ks][2], aA[p * 4 + ks][3], b0, b2r);
                    mma16816(hh1, aA[p * 4 + ks][0], aA[p * 4 + ks][1],
                             aA[p * 4 + ks][2], aA[p * 4 + ks][3], b1r, b3);
                }
            int hc = j * 128 + ks2 * 16;
            float v00 = fmaxf(hh0[0] + s_b1[hc + qc],     0.0f);
            float v01 = fmaxf(hh0[1] + s_b1[hc + qc + 1], 0.0f);
            float v02 = fmaxf(hh0[2] + s_b1[hc + qc],     0.0f);
            float v03 = fmaxf(hh0[3] + s_b1[hc + qc + 1], 0.0f);
            float v10 = fmaxf(hh1[0] + s_b1[hc + 8 + qc],     0.0f);
            float v11 = fmaxf(hh1[1] + s_b1[hc + 8 + qc + 1], 0.0f);
            float v12 = fmaxf(hh1[2] + s_b1[hc + 8 + qc],     0.0f);
            float v13 = fmaxf(hh1[3] + s_b1[hc + 8 + qc + 1], 0.0f);
            uint32_t fa0 = pack_bf16(v00, v01);
            uint32_t fa1 = pack_bf16(v02, v03);
            uint32_t fa2 = pack_bf16(v10, v11);
            uint32_t fa3 = pack_bf16(v12, v13);
            int p2 = ks2 >> 2, kk = ks2 & 3;
#pragma unroll
            for (int nb = 0; nb < 8; nb++) {
                uint32_t b0, b1r, b2r, b3;
                uint32_t baddr = smem_u32(&sW2[p2 * 9216 +
                                               (nb * 16 + (lane & 15)) * 72 +
                                               kk * 16 + (lane >> 4) * 8]);
                ldsm4(b0, b1r, b2r, b3, baddr);
                mma16816(co[nb * 2 + 0], fa0, fa1, fa2, fa3, b0, b2r);
                mma16816(co[nb * 2 + 1], fa0, fa1, fa2, fa3, b1r, b3);
            }
        }
    }

    const int r0 = row0 + wid * 16 + qr;
    const int r1 = r0 + 8;
    float s0 = 0.f, q0 = 0.f, s1 = 0.f, q1 = 0.f;
#pragma unroll
    for (int b = 0; b < 16; b++) {
        int lcn = b * 8 + qc;
        float2 rv0 = *(const float2*)&qin[(size_t)r0 * 128 + lcn];
        float2 rv1 = *(const float2*)&qin[(size_t)r1 * 128 + lcn];
        co[b][0] += s_b2[lcn]     + rv0.x;
        co[b][1] += s_b2[lcn + 1] + rv0.y;
        co[b][2] += s_b2[lcn]     + rv1.x;
        co[b][3] += s_b2[lcn + 1] + rv1.y;
        s0 += co[b][0] + co[b][1];  q0 += co[b][0] * co[b][0] + co[b][1] * co[b][1];
        s1 += co[b][2] + co[b][3];  q1 += co[b][2] * co[b][2] + co[b][3] * co[b][3];
    }
#pragma unroll
    for (int o = 1; o <= 2; o <<= 1) {
        s0 += __shfl_xor_sync(0xffffffffu, s0, o);
        q0 += __shfl_xor_sync(0xffffffffu, q0, o);
        s1 += __shfl_xor_sync(0xffffffffu, s1, o);
        q1 += __shfl_xor_sync(0xffffffffu, q1, o);
    }
    float m0 = s0 * (1.0f / 128.0f);
    float i0 = rsqrtf(q0 * (1.0f / 128.0f) - m0 * m0 + 1e-5f);
    float m1 = s1 * (1.0f / 128.0f);
    float i1 = rsqrtf(q1 * (1.0f / 128.0f) - m1 * m1 + 1e-5f);
#pragma unroll
    for (int b = 0; b < 16; b++) {
        int lcn = b * 8 + qc;
        float2 o0, o1;
        o0.x = (co[b][0] - m0) * i0 * s_g[lcn]     + s_b[lcn];
        o0.y = (co[b][1] - m0) * i0 * s_g[lcn + 1] + s_b[lcn + 1];
        o1.x = (co[b][2] - m1) * i1 * s_g[lcn]     + s_b[lcn];
        o1.y = (co[b][3] - m1) * i1 * s_g[lcn + 1] + s_b[lcn + 1];
        *(float2*)&outp[(size_t)r0 * 128 + lcn] = o0;
        *(float2*)&outp[(size_t)r1 * 128 + lcn] = o1;
    }
}

// ---------------------------------------------------------------------------
extern "C" void kernel_launch(void* const* d_in, const int* in_sizes, int n_in,
                              void* d_out, int out_size)
{
    const float* query = (const float*)d_in[0];
    const float* src   = (const float*)d_in[1];
    const float* pos   = (const float*)d_in[2];
    const float* so_w  = (const float*)d_in[3];
    const float* so_b  = (const float*)d_in[4];
    const float* aw_w  = (const float*)d_in[5];
    const float* aw_b  = (const float*)d_in[6];
    const float* vp_w  = (const float*)d_in[7];
    const float* vp_b  = (const float*)d_in[8];
    const float* op_w  = (const float*)d_in[9];
    const float* op_b  = (const float*)d_in[10];
    const float* ln1_g = (const float*)d_in[11];
    const float* ln1_b = (const float*)d_in[12];
    const float* l1_w  = (const float*)d_in[13];
    const float* l1_b  = (const float*)d_in[14];
    const float* l2_w  = (const float*)d_in[15];
    const float* l2_b  = (const float*)d_in[16];
    const float* ln2_g = (const float*)d_in[17];
    const float* ln2_b = (const float*)d_in[18];

    float* qbuf;
    __nv_bfloat16 *vbuf, *wbuf, *wsobuf;
    cudaGetSymbolAddress((void**)&qbuf, g_q);
    cudaGetSymbolAddress((void**)&vbuf, g_value);
    cudaGetSymbolAddress((void**)&wbuf, g_wb);
    cudaGetSymbolAddress((void**)&wsobuf, g_wso);

    cudaFuncSetAttribute(ffn_fused<true>,  cudaFuncAttributeMaxDynamicSharedMemorySize, FFN_SMEM);
    cudaFuncSetAttribute(ffn_fused<false>, cudaFuncAttributeMaxDynamicSharedMemorySize, FFN_SMEM);
    cudaFuncSetAttribute(attn_fused, cudaFuncAttributeMaxDynamicSharedMemorySize, ATT_SMEM);
    cudaFuncSetAttribute(gemm_vp, cudaFuncAttributeMaxDynamicSharedMemorySize, VP_SMEM);

    prep_weights<<<(PREP_TOTAL + 255) / 256, 256>>>(vp_w, op_w, l1_w, l2_w, so_w, aw_w);
    // layer-0 value projection only (layer 1 co-scheduled with ffn-l0)
    gemm_vp<<<NTOK / 128, 256, VP_SMEM>>>(src, vp_b);

    for (int l = 0; l < 2; l++) {
        const __nv_bfloat16* wb = wbuf + (size_t)l * WB_LAYER;
        const float* qsrc = (l == 0) ? query : qbuf;
        float* ffn_out = (l == 0) ? qbuf : (float*)d_out;
        attn_fused<<<NTOK / 64, 256, ATT_SMEM>>>(
            vbuf + (size_t)l * NTOK * DM, wb + WB_OP, op_b + l * DM,
            so_b + l * 32, aw_b + l * 16, qsrc, pos,
            wsobuf + (size_t)l * 8192, ln1_g + l * DM, ln1_b + l * DM, qbuf);
        if (l == 0) {
            ffn_fused<true><<<2 * FFN_GRID, 256, FFN_SMEM>>>(
                qbuf, wb + WB_L1, l1_b + l * FFD, wb + WB_L2, l2_b + l * DM,
                ln2_g + l * DM, ln2_b + l * DM, ffn_out, src, vp_b);
        } else {
            ffn_fused<false><<<FFN_GRID, 256, FFN_SMEM>>>(
                qbuf, wb + WB_L1, l1_b + l * FFD, wb + WB_L2, l2_b + l * DM,
                ln2_g + l * DM, ln2_b + l * DM, ffn_out, nullptr, nullptr);
        }
    }
}